// round 6
// baseline (speedup 1.0000x reference)
#include <cuda_runtime.h>

// NF4 blockwise quant-dequant (blocksize 512).
// One warp per 512-element quant block: 32 lanes x 16 elements (4x float4).
// R4 content, third submission (two infra failures; removed math.h/INFINITY
// from the device-global initializer as the only plausible source irritant):
//  (a) 2 shuffles/element instead of 3, using vhi[k] == vlo[k+1]:
//      t = shfl(thr,k); j = k + (x > t); val = shfl(vlo, j)
//  (b) compile-time per-lane bucket table (one coalesced LDG.64) instead of
//      ~100-instr runtime construction -> fewer regs, higher occupancy
//  (c) streaming cache hints (__ldcs/__stcs), data touched exactly once.

#define NQB_PER_CTA 8

// NF4 codebook (exact bitsandbytes constants)
#define C0  (-1.0f)
#define C1  (-0.6961928009986877f)
#define C2  (-0.5250730514526367f)
#define C3  (-0.39491748809814453f)
#define C4  (-0.28444138169288635f)
#define C5  (-0.18477343022823334f)
#define C6  (-0.09105003625154495f)
#define C7  (0.0f)
#define C8  (0.07958029955625534f)
#define C9  (0.16093020141124725f)
#define C10 (0.24611230194568634f)
#define C11 (0.33791524171829224f)
#define C12 (0.4407098591327667f)
#define C13 (0.5626170039176941f)
#define C14 (0.7229568362236023f)
#define C15 (1.0f)
// Decision boundaries: exact fp32 midpoints (folded at compile time, RN)
#define M0  ((C0  + C1 ) * 0.5f)
#define M1  ((C1  + C2 ) * 0.5f)
#define M2  ((C2  + C3 ) * 0.5f)
#define M3  ((C3  + C4 ) * 0.5f)
#define M4  ((C4  + C5 ) * 0.5f)
#define M5  ((C5  + C6 ) * 0.5f)
#define M6  ((C6  + C7 ) * 0.5f)
#define M7  ((C7  + C8 ) * 0.5f)
#define M8  ((C8  + C9 ) * 0.5f)
#define M9  ((C9  + C10) * 0.5f)
#define M10 ((C10 + C11) * 0.5f)
#define M11 ((C11 + C12) * 0.5f)
#define M12 ((C12 + C13) * 0.5f)
#define M13 ((C13 + C14) * 0.5f)
#define M14 ((C14 + C15) * 0.5f)
// "No boundary in this bucket" sentinel: huge finite fp32. Inputs satisfy
// |x| <= absmax, and SENT*scale >= SENT (or +inf) for scale >= 1, while for
// scale < 1 SENT*scale still dwarfs absmax. x > sentinel is always false.
#define SENT (3.0e38f)

// Bucket k covers xn in [k/16 - 1, (k+1)/16 - 1). Width 1/16 < min boundary
// gap (0.0805) => at most one boundary per bucket.
// tbl[k] = { threshold-in-bucket (or SENT), codebook value at bucket start }.
// Value above the threshold == vlo of bucket k+1 (looked up via j = k+1).
__device__ const float2 g_tbl[32] = {
    {SENT, C0 }, {SENT, C0 }, {M0,   C0 }, {SENT, C1 },
    {SENT, C1 }, {SENT, C1 }, {M1,   C1 }, {SENT, C2 },
    {M2,   C2 }, {SENT, C3 }, {M3,   C3 }, {SENT, C4 },
    {M4,   C4 }, {M5,   C5 }, {SENT, C6 }, {M6,   C6 },
    {M7,   C7 }, {M8,   C8 }, {SENT, C9 }, {M9,   C9 },
    {M10,  C10}, {SENT, C11}, {M11,  C11}, {SENT, C12},
    {M12,  C12}, {SENT, C13}, {M13,  C13}, {SENT, C14},
    {SENT, C14}, {M14,  C14}, {SENT, C15}, {SENT, C15}
};

__global__ __launch_bounds__(256) void nf4_qdq_kernel(
    const float* __restrict__ x, float* __restrict__ out, long long n_qb) {
    int warp = threadIdx.x >> 5;
    int lane = threadIdx.x & 31;
    long long qb = (long long)blockIdx.x * NQB_PER_CTA + warp;
    if (qb >= n_qb) return;   // warp-uniform; no barriers anywhere

    // Per-lane bucket entry (lane == bucket), one coalesced 8B load, L1-hot.
    float2 te = g_tbl[lane];

    const float4* __restrict__ in4  = (const float4*)(x   + qb * 512);
    float4*       __restrict__ out4 = (float4*)      (out + qb * 512);

    // 16 elements per lane, 4x coalesced 128-bit streaming loads (MLP=4)
    float4 v[4];
    #pragma unroll
    for (int i = 0; i < 4; i++) v[i] = __ldcs(&in4[i * 32 + lane]);

    // Blockwise absmax: register FMNMX then warp butterfly (exact)
    float m = 0.0f;
    #pragma unroll
    for (int i = 0; i < 4; i++) {
        m = fmaxf(m, fabsf(v[i].x));
        m = fmaxf(m, fabsf(v[i].y));
        m = fmaxf(m, fabsf(v[i].z));
        m = fmaxf(m, fabsf(v[i].w));
    }
    #pragma unroll
    for (int s = 16; s; s >>= 1)
        m = fmaxf(m, __shfl_xor_sync(0xffffffffu, m, s));

    float absmax = m;
    float scale  = (absmax == 0.0f) ? 1.0f : absmax;
    float s16    = __frcp_rn(scale) * 16.0f;  // bucketing only; edge-tolerant

    // Scale into raw-x domain (once per warp). SENT*scale stays >> any |x|
    // (overflow to +inf is fine), so "no boundary" buckets never flip.
    float thr_s = te.x * scale;    // compare x > thr*scale  ~  x/scale > thr
    float vlo_s = te.y * absmax;   // same RN mul as reference NF4[idx]*absmax

    #pragma unroll
    for (int i = 0; i < 4; i++) {
        float4 r;
        #pragma unroll
        for (int e = 0; e < 4; e++) {
            float xv = (&v[i].x)[e];
            float kf = fmaf(xv, s16, 16.0f);       // bucket in [0,32]
            int k = min((int)kf, 31);              // trunc; -eps -> 0
            float t = __shfl_sync(0xffffffffu, thr_s, k);
            int j = k + ((xv > t) ? 1 : 0);        // above boundary -> next vlo
            (&r.x)[e] = __shfl_sync(0xffffffffu, vlo_s, j);
        }
        __stcs(&out4[i * 32 + lane], r);
    }
}

extern "C" void kernel_launch(void* const* d_in, const int* in_sizes, int n_in,
                              void* d_out, int out_size) {
    const float* x = (const float*)d_in[0];
    float* out = (float*)d_out;
    long long n = (long long)in_sizes[0];
    long long n_qb = n / 512;                 // n is a multiple of 512
    int grid = (int)((n_qb + NQB_PER_CTA - 1) / NQB_PER_CTA);
    nf4_qdq_kernel<<<grid, 256>>>(x, out, n_qb);
}